// round 13
// baseline (speedup 1.0000x reference)
#include <cuda_runtime.h>
#include <cuda_bf16.h>
#include <cuda_fp16.h>
#include <cstdint>
#include <math.h>

#define NN 100000
#define EE 3200000
#define NB 98  // ceil(NN/1024)

#define SCAT_BLOCKS ((EE / 2 + 255) / 256)   // 6250  (2 edges per thread)
#define CAST_BLOCKS ((NN * 32 + 255) / 256)  // 12500 (uint4 per thread)

// ---------------- device scratch (static, no runtime alloc) ----------------
__device__ int   g_is64;
__device__ int   g_deg[NN];
__device__ float g_dis[NN];
__device__ int   g_off[NN + 1];
__device__ int   g_cur[NN];
__device__ int   g_bsum[NB];
__device__ int   g_srcs[EE];                       // CSR-sorted src per dst
__device__ uint4 g_x16   [(size_t)NN * 32];        // fp16 dis-scaled [latent|cond]
__device__ uint4 g_xagg16[(size_t)NN * 32];        // fp16 aggregated features (256)
__device__ uint4 g_act16 [(size_t)NN * 64];        // fp16 tanh activations (512)
__device__ uint2 g_h16   [(size_t)NN * 32];        // fp16 dis-scaled h2 (128)
__device__ __half g_w16z[128 * 256];               // fp16 Wz
__device__ __half g_w16c[128 * 256];               // fp16 Wc
__device__ __half g_w16o[512 * 128];               // fp16 Wo

// ==================== warp-MMA helpers (sm_80+ HMMA path) ====================
__device__ __forceinline__ uint32_t smem_u32(const void* p) {
    uint32_t a;
    asm("{ .reg .u64 t; cvta.to.shared.u64 t, %1; cvt.u32.u64 %0, t; }" : "=r"(a) : "l"(p));
    return a;
}

// fp16 x fp16 -> fp32 accumulate
__device__ __forceinline__ void mma16816h(float* d, const uint32_t* a, const uint32_t* b) {
    asm volatile(
        "mma.sync.aligned.m16n8k16.row.col.f32.f16.f16.f32 "
        "{%0,%1,%2,%3}, {%4,%5,%6,%7}, {%8,%9}, {%0,%1,%2,%3};"
        : "+f"(d[0]), "+f"(d[1]), "+f"(d[2]), "+f"(d[3])
        : "r"(a[0]), "r"(a[1]), "r"(a[2]), "r"(a[3]), "r"(b[0]), "r"(b[1]));
}

__device__ __forceinline__ void ldmx4(uint32_t* r, uint32_t addr) {
    asm volatile("ldmatrix.sync.aligned.m8n8.x4.shared.b16 {%0,%1,%2,%3}, [%4];"
                 : "=r"(r[0]), "=r"(r[1]), "=r"(r[2]), "=r"(r[3]) : "r"(addr));
}
__device__ __forceinline__ void ldmx4t(uint32_t* r, uint32_t addr) {
    asm volatile("ldmatrix.sync.aligned.m8n8.x4.trans.shared.b16 {%0,%1,%2,%3}, [%4];"
                 : "=r"(r[0]), "=r"(r[1]), "=r"(r[2]), "=r"(r[3]) : "r"(addr));
}

// pack fp32x4 -> fp16x4 (round-to-nearest)
__device__ __forceinline__ uint2 pack4h(float4 v) {
    uint2 u;
    __half2 a = __floats2half2_rn(v.x, v.y);
    __half2 b = __floats2half2_rn(v.z, v.w);
    u.x = *(uint32_t*)&a;
    u.y = *(uint32_t*)&b;
    return u;
}

// ==================== fp16 GEMM, double-buffered w/ register prefetch ================
// 128x128 block, 8 warps of 32x64. A: [NN, LDA] fp16. W16: [KTOT, ldw] fp16 @ncol0.
// D = A@W (fp32 accum). One __syncthreads per K-chunk; loads for chunk k+1 are in
// flight (registers) while chunk k's MMAs run; stores target the other smem buffer.
// Output: H16 ? g_h16[row] = half2(dis[row]*D) : C[row] = half2(op(D + bias))
template <int KTOT, int LDA, int LDC, bool TANH, bool HASB, bool H16>
__device__ __forceinline__ void gemm_mma(const __half* __restrict__ A,
                                         const __half* __restrict__ W16, int ldw,
                                         const float* __restrict__ bias,
                                         __half* __restrict__ C,
                                         int row0, int ncol0) {
    constexpr int CH = KTOT / 32;
    __shared__ __align__(16) uint16_t sA[2][128 * 40];   // stride 40 halves
    __shared__ __align__(16) uint16_t sB[2][32 * 136];   // stride 136 halves

    int tid = threadIdx.x, lane = tid & 31, wid = tid >> 5;
    int wm = wid & 3, wn = wid >> 2;  // warp tile: rows [wm*32,+32), cols [wn*64,+64)

    float acc[2][8][4];
    #pragma unroll
    for (int i = 0; i < 2; i++)
        #pragma unroll
        for (int j = 0; j < 8; j++)
            #pragma unroll
            for (int k = 0; k < 4; k++) acc[i][j][k] = 0.f;

    uint32_t aA = smem_u32(sA), aB = smem_u32(sB);
    uint32_t offA0 = (uint32_t)(((wm * 32 + (lane & 15)) * 40 + ((lane >> 4) << 3)) * 2);
    uint32_t offB0 = (uint32_t)(((lane & 15) * 136 + wn * 64 + ((lane >> 4) << 3)) * 2);

    // per-thread staging coordinates
    int ar0 = tid >> 2,        ac0 = (tid & 3) * 8;         // A slot 0
    int ar1 = (tid + 256) >> 2, ac1 = ((tid + 256) & 3) * 8; // A slot 1
    auto loadA = [&](int ch, uint4* areg) {
        int g0 = row0 + ar0, g1 = row0 + ar1;
        areg[0] = (g0 < NN) ? *(const uint4*)(A + (size_t)g0 * LDA + ch * 32 + ac0)
                            : make_uint4(0u, 0u, 0u, 0u);
        areg[1] = (g1 < NN) ? *(const uint4*)(A + (size_t)g1 * LDA + ch * 32 + ac1)
                            : make_uint4(0u, 0u, 0u, 0u);
    };
    auto storeA = [&](int buf, const uint4* areg) {
        *(uint4*)((char*)sA[buf] + (ar0 * 40 + ac0) * 2) = areg[0];
        *(uint4*)((char*)sA[buf] + (ar1 * 40 + ac1) * 2) = areg[1];
    };
    auto loadB = [&](int ch, uint2* breg) {
        #pragma unroll
        for (int i = 0; i < 4; i++) {
            int lin = tid + 256 * i;
            int kr = lin >> 5, c4 = lin & 31;
            breg[i] = *(const uint2*)(W16 + (size_t)(ch * 32 + kr) * ldw + ncol0 + c4 * 4);
        }
    };
    auto storeB = [&](int buf, const uint2* breg) {
        #pragma unroll
        for (int i = 0; i < 4; i++) {
            int lin = tid + 256 * i;
            int kr = lin >> 5, c4 = lin & 31;
            *(uint2*)((char*)sB[buf] + (kr * 136 + c4 * 4) * 2) = breg[i];
        }
    };

    // prologue: chunk 0 -> buffer 0
    {
        uint4 a0[2];
        uint2 b0[4];
        loadA(0, a0);
        loadB(0, b0);
        storeA(0, a0);
        storeB(0, b0);
    }

    for (int ch = 0; ch < CH; ch++) {
        int buf = ch & 1;
        bool more = (ch + 1 < CH);
        uint4 areg[2];
        uint2 breg[4];
        if (more) { loadA(ch + 1, areg); loadB(ch + 1, breg); }  // in-flight during MMAs
        __syncthreads();  // buf's stores visible to all
        uint32_t bufA = aA + buf * 10240;
        uint32_t bufB = aB + buf * 8704;
        #pragma unroll
        for (int kb = 0; kb < 32; kb += 16) {
            uint32_t a[2][4], bb[4][4];
            #pragma unroll
            for (int mi = 0; mi < 2; mi++)
                ldmx4(a[mi], bufA + offA0 + (uint32_t)((mi * 16 * 40 + kb) * 2));
            #pragma unroll
            for (int g = 0; g < 4; g++)
                ldmx4t(bb[g], bufB + offB0 + (uint32_t)((kb * 136 + g * 16) * 2));
            #pragma unroll
            for (int mi = 0; mi < 2; mi++)
                #pragma unroll
                for (int g = 0; g < 4; g++) {
                    mma16816h(acc[mi][2 * g],     a[mi], &bb[g][0]);
                    mma16816h(acc[mi][2 * g + 1], a[mi], &bb[g][2]);
                }
        }
        // store chunk ch+1 into the other buffer; safe: that buffer's reads finished
        // before THIS iteration's __syncthreads (ldmatrix results land in registers).
        if (more) { storeA(buf ^ 1, areg); storeB(buf ^ 1, breg); }
    }
    __syncthreads();

    // ---- epilogue: half2 outputs
    int rbase = row0 + wm * 32 + (lane >> 2);
    #pragma unroll
    for (int mi = 0; mi < 2; mi++)
        #pragma unroll
        for (int h = 0; h < 2; h++) {
            int gr = rbase + mi * 16 + h * 8;
            if (gr >= NN) continue;
            float dd = H16 ? g_dis[gr] : 1.f;
            #pragma unroll
            for (int ni = 0; ni < 8; ni++) {
                int cl = wn * 64 + ni * 8 + (lane & 3) * 2;
                float v0 = acc[mi][ni][2 * h];
                float v1 = acc[mi][ni][2 * h + 1];
                if (HASB) { v0 += bias[cl]; v1 += bias[cl + 1]; }
                if (TANH) { v0 = tanhf(v0); v1 = tanhf(v1); }
                if (H16) {
                    ((__half2*)g_h16)[(size_t)gr * 64 + (cl >> 1)] =
                        __floats2half2_rn(dd * v0, dd * v1);
                } else {
                    *(__half2*)(C + (size_t)gr * LDC + cl) = __floats2half2_rn(v0, v1);
                }
            }
        }
}

__global__ void __launch_bounds__(256, 2) gemm_zc_mma(const float* __restrict__ bz,
                                                      const float* __restrict__ bc) {
    int conv = blockIdx.z;
    int nb = blockIdx.y * 128;
    const __half* W = conv ? g_w16c : g_w16z;
    const float* b = conv ? bc : bz;
    gemm_mma<128, 256, 512, true, true, false>(
        (const __half*)g_xagg16 + conv * 128, W, 256, b + nb,
        (__half*)g_act16 + conv * 256 + nb, blockIdx.x * 128, nb);
}

__global__ void __launch_bounds__(256, 2) gemm_o_mma() {
    gemm_mma<512, 512, 128, false, false, true>(
        (const __half*)g_act16, g_w16o, 128, nullptr, nullptr, blockIdx.x * 128, 0);
}

// ---------------- fused dtype detect + degree init + W fp16 precompute -------
__global__ void detect_init_kernel(const unsigned int* __restrict__ w,
                                   const float* __restrict__ Wz,
                                   const float* __restrict__ Wc,
                                   const float* __restrict__ Wo) {
    int i = blockIdx.x * blockDim.x + threadIdx.x;
    if (i < NN) g_deg[i] = 1;  // self loop pre-counted
    // W fp32 -> fp16 (same __floats2half2_rn rounding as the old per-tile path)
    if (i < 8192) {
        ((uint2*)g_w16z)[i] = pack4h(((const float4*)Wz)[i]);
    } else if (i < 16384) {
        ((uint2*)g_w16c)[i - 8192] = pack4h(((const float4*)Wc)[i - 8192]);
    } else if (i < 32768) {
        ((uint2*)g_w16o)[i - 16384] = pack4h(((const float4*)Wo)[i - 16384]);
    }
    if (blockIdx.x == 0) {
        // If int64 (LE), high word of every value (<100000) is 0; sample 2048.
        int bad = 0;
        for (int k = threadIdx.x; k < 2048; k += blockDim.x)
            if (w[2 * k + 1] != 0u) bad = 1;
        if (__syncthreads_or(bad)) {
            if (threadIdx.x == 0) g_is64 = 0;
        } else {
            if (threadIdx.x == 0) g_is64 = 1;
        }
    }
}

// ---------------- degree count (2 edges/thread, vectorized decode) -----------
__global__ void count_kernel(const void* __restrict__ ei) {
    int e2 = blockIdx.x * blockDim.x + threadIdx.x;  // pair index
    if (e2 >= EE / 2) return;
    int d0, d1;
    if (g_is64) {
        const longlong2* pd = (const longlong2*)((const long long*)ei + EE);
        longlong2 dv = pd[e2];
        d0 = (int)dv.x; d1 = (int)dv.y;
    } else {
        const int2* pd = (const int2*)((const int*)ei + EE);
        int2 dv = pd[e2];
        d0 = dv.x; d1 = dv.y;
    }
    atomicAdd(&g_deg[d0], 1);
    atomicAdd(&g_deg[d1], 1);
}

__global__ void scan1_kernel() {
    __shared__ int sh[1024];
    int i = blockIdx.x * 1024 + threadIdx.x;
    int v = 0;
    if (i < NN) {
        int d = g_deg[i];
        g_dis[i] = rsqrtf((float)d);
        v = d - 1;
    }
    sh[threadIdx.x] = v;
    __syncthreads();
    for (int ofs = 1; ofs < 1024; ofs <<= 1) {
        int t = 0;
        if ((int)threadIdx.x >= ofs) t = sh[threadIdx.x - ofs];
        __syncthreads();
        sh[threadIdx.x] += t;
        __syncthreads();
    }
    int incl = sh[threadIdx.x];
    if (i < NN) g_off[i] = incl - v;  // exclusive within block
    if (threadIdx.x == 1023) g_bsum[blockIdx.x] = incl;
}

// scan3 with scan2 folded in: every block redundantly scans the 98 block sums.
__global__ void scan3_kernel() {
    __shared__ int sh[128];
    int t = threadIdx.x;
    if (t < 128) {
        int v = (t < NB) ? g_bsum[t] : 0;
        sh[t] = v;
        __syncthreads();
        for (int ofs = 1; ofs < 128; ofs <<= 1) {
            int u = (t >= ofs) ? sh[t - ofs] : 0;
            __syncthreads();
            sh[t] += u;
            __syncthreads();
        }
        if (t < 128) sh[t] -= v;  // exclusive
    } else {
        for (int ofs = 1; ofs < 128; ofs <<= 1) { __syncthreads(); __syncthreads(); }
    }
    __syncthreads();
    int base = sh[blockIdx.x];
    int i = blockIdx.x * 1024 + t;
    if (i < NN) {
        int o = g_off[i] + base;
        g_off[i] = o;
        g_cur[i] = o;
    }
    if (i == 0) g_off[NN] = EE;
}

// ---------------- fused scatter (CSR fill, 2 edges/thread) + cast (uint4/thread)
__global__ void __launch_bounds__(256) scatter_cast_kernel(
        const void* __restrict__ ei,
        const float* __restrict__ lat, const float* __restrict__ cond) {
    int b = blockIdx.x;
    if (b < SCAT_BLOCKS) {
        int e2 = b * 256 + threadIdx.x;  // pair index
        if (e2 >= EE / 2) return;
        int s0, s1, d0, d1;
        if (g_is64) {
            const longlong2* ps = (const longlong2*)ei;
            const longlong2* pd = (const longlong2*)((const long long*)ei + EE);
            longlong2 sv = ps[e2];
            longlong2 dv = pd[e2];
            s0 = (int)sv.x; s1 = (int)sv.y;
            d0 = (int)dv.x; d1 = (int)dv.y;
        } else {
            const int2* ps = (const int2*)ei;
            const int2* pd = (const int2*)((const int*)ei + EE);
            int2 sv = ps[e2];
            int2 dv = pd[e2];
            s0 = sv.x; s1 = sv.y;
            d0 = dv.x; d1 = dv.y;
        }
        g_srcs[atomicAdd(&g_cur[d0], 1)] = s0;
        g_srcs[atomicAdd(&g_cur[d1], 1)] = s1;
    } else {
        int t = (b - SCAT_BLOCKS) * 256 + threadIdx.x;  // over NN*32 uint4 slots
        if (t >= NN * 32) return;
        int node = t >> 5;
        int c8 = t & 31;   // which 8-half group of the 256-wide row
        float dd = g_dis[node];
        const float4* src = (c8 < 16)
            ? ((const float4*)lat  + (size_t)node * 32 + 2 * c8)
            : ((const float4*)cond + (size_t)node * 32 + 2 * (c8 - 16));
        float4 v0 = src[0];
        float4 v1 = src[1];
        uint4 o;
        __half2* oh = (__half2*)&o;
        oh[0] = __floats2half2_rn(dd * v0.x, dd * v0.y);
        oh[1] = __floats2half2_rn(dd * v0.z, dd * v0.w);
        oh[2] = __floats2half2_rn(dd * v1.x, dd * v1.y);
        oh[3] = __floats2half2_rn(dd * v1.z, dd * v1.w);
        g_x16[(size_t)node * 32 + c8] = o;
    }
}

// ---------------- unpack-accumulate helpers ----------------
__device__ __forceinline__ void acc8(float* a, uint4 v) {
    const __half2* h = (const __half2*)&v;
    #pragma unroll
    for (int k = 0; k < 4; k++) {
        float2 f = __half22float2(h[k]);
        a[2 * k] += f.x;
        a[2 * k + 1] += f.y;
    }
}
__device__ __forceinline__ void acc4(float* a, uint2 v) {
    const __half2* h = (const __half2*)&v;
    float2 f0 = __half22float2(h[0]);
    float2 f1 = __half22float2(h[1]);
    a[0] += f0.x; a[1] += f0.y; a[2] += f1.x; a[3] += f1.y;
}

// ---------------- aggregation 1: fp16 gather, 512B/node, warp-per-node -----
__global__ void __launch_bounds__(256) aggx_kernel() {
    int gw = (int)((blockIdx.x * blockDim.x + threadIdx.x) >> 5);
    int lane = threadIdx.x & 31;
    if (gw >= NN) return;
    float dd = g_dis[gw];
    float a[8];
    #pragma unroll
    for (int k = 0; k < 8; k++) a[k] = 0.f;
    acc8(a, g_x16[(size_t)gw * 32 + lane]);  // self term (pre-scaled by dis)
    int beg = g_off[gw], end = g_off[gw + 1];
    #pragma unroll 4
    for (int j = beg; j < end; ++j) {
        int s = g_srcs[j];
        acc8(a, g_x16[(size_t)s * 32 + lane]);
    }
    uint4 o;
    __half2* oh = (__half2*)&o;
    #pragma unroll
    for (int k = 0; k < 4; k++)
        oh[k] = __floats2half2_rn(dd * a[2 * k], dd * a[2 * k + 1]);
    g_xagg16[(size_t)gw * 32 + lane] = o;
}

// ---------------- aggregation 2: fp16 gather, 256B/node, warp-per-node -----
__global__ void __launch_bounds__(256) agg2_kernel(const float* __restrict__ bo,
                                                   float* __restrict__ out) {
    int gw = (int)((blockIdx.x * blockDim.x + threadIdx.x) >> 5);
    int lane = threadIdx.x & 31;
    if (gw >= NN) return;
    float dd = g_dis[gw];
    float a[4];
    #pragma unroll
    for (int k = 0; k < 4; k++) a[k] = 0.f;
    acc4(a, g_h16[(size_t)gw * 32 + lane]);  // self term
    int beg = g_off[gw], end = g_off[gw + 1];
    #pragma unroll 4
    for (int j = beg; j < end; ++j) {
        int s = g_srcs[j];
        acc4(a, g_h16[(size_t)s * 32 + lane]);
    }
    float4 b = ((const float4*)bo)[lane];
    ((float4*)out)[(size_t)gw * 32 + lane] =
        make_float4(dd * a[0] + b.x, dd * a[1] + b.y, dd * a[2] + b.z, dd * a[3] + b.w);
}

// ---------------- launch ----------------
extern "C" void kernel_launch(void* const* d_in, const int* in_sizes, int n_in,
                              void* d_out, int out_size) {
    const float* latent    = (const float*)d_in[0];
    const float* condition = (const float*)d_in[1];
    const void*  ei        = d_in[2];
    const float* Wz = (const float*)d_in[3];
    const float* bz = (const float*)d_in[4];
    const float* Wc = (const float*)d_in[5];
    const float* bc = (const float*)d_in[6];
    const float* Wo = (const float*)d_in[7];
    const float* bo = (const float*)d_in[8];
    float* out = (float*)d_out;

    detect_init_kernel<<<(NN + 255) / 256, 256>>>((const unsigned int*)ei, Wz, Wc, Wo);
    count_kernel<<<(EE / 2 + 255) / 256, 256>>>(ei);
    scan1_kernel<<<NB, 1024>>>();
    scan3_kernel<<<NB, 1024>>>();
    scatter_cast_kernel<<<SCAT_BLOCKS + CAST_BLOCKS, 256>>>(ei, latent, condition);
    aggx_kernel<<<(NN * 32 + 255) / 256, 256>>>();

    int ntiles = (NN + 127) / 128;  // 782
    gemm_zc_mma<<<dim3(ntiles, 2, 2), 256>>>(bz, bc);
    gemm_o_mma<<<ntiles, 256>>>();

    agg2_kernel<<<(NN * 32 + 255) / 256, 256>>>(bo, out);
}

// round 14
// speedup vs baseline: 1.4057x; 1.4057x over previous
#include <cuda_runtime.h>
#include <cuda_bf16.h>
#include <cuda_fp16.h>
#include <cstdint>
#include <math.h>

#define NN 100000
#define EE 3200000
#define NB 98  // ceil(NN/1024)

#define SCAT_BLOCKS ((EE / 2 + 255) / 256)   // 6250  (2 edges per thread)
#define CAST_BLOCKS ((NN * 32 + 255) / 256)  // 12500 (uint4 per thread)

// ---------------- device scratch (static, no runtime alloc) ----------------
__device__ int   g_is64;
__device__ int   g_deg[NN];
__device__ float g_dis[NN];
__device__ int   g_off[NN + 1];
__device__ int   g_cur[NN];
__device__ int   g_bsum[NB];
__device__ int   g_srcs[EE];                       // CSR-sorted src per dst
__device__ uint4 g_x16   [(size_t)NN * 32];        // fp16 dis-scaled [latent|cond]
__device__ uint4 g_xagg16[(size_t)NN * 32];        // fp16 aggregated features (256)
__device__ uint4 g_act16 [(size_t)NN * 64];        // fp16 tanh activations (512)
__device__ uint2 g_h16   [(size_t)NN * 32];        // fp16 dis-scaled h2 (128)

// ==================== warp-MMA helpers (sm_80+ HMMA path) ====================
__device__ __forceinline__ uint32_t smem_u32(const void* p) {
    uint32_t a;
    asm("{ .reg .u64 t; cvta.to.shared.u64 t, %1; cvt.u32.u64 %0, t; }" : "=r"(a) : "l"(p));
    return a;
}

// fp16 x fp16 -> fp32 accumulate
__device__ __forceinline__ void mma16816h(float* d, const uint32_t* a, const uint32_t* b) {
    asm volatile(
        "mma.sync.aligned.m16n8k16.row.col.f32.f16.f16.f32 "
        "{%0,%1,%2,%3}, {%4,%5,%6,%7}, {%8,%9}, {%0,%1,%2,%3};"
        : "+f"(d[0]), "+f"(d[1]), "+f"(d[2]), "+f"(d[3])
        : "r"(a[0]), "r"(a[1]), "r"(a[2]), "r"(a[3]), "r"(b[0]), "r"(b[1]));
}

__device__ __forceinline__ void ldmx4(uint32_t* r, uint32_t addr) {
    asm volatile("ldmatrix.sync.aligned.m8n8.x4.shared.b16 {%0,%1,%2,%3}, [%4];"
                 : "=r"(r[0]), "=r"(r[1]), "=r"(r[2]), "=r"(r[3]) : "r"(addr));
}
__device__ __forceinline__ void ldmx4t(uint32_t* r, uint32_t addr) {
    asm volatile("ldmatrix.sync.aligned.m8n8.x4.trans.shared.b16 {%0,%1,%2,%3}, [%4];"
                 : "=r"(r[0]), "=r"(r[1]), "=r"(r[2]), "=r"(r[3]) : "r"(addr));
}

// pack fp32x4 -> fp16x4 (round-to-nearest)
__device__ __forceinline__ uint2 pack4h(float4 v) {
    uint2 u;
    __half2 a = __floats2half2_rn(v.x, v.y);
    __half2 b = __floats2half2_rn(v.z, v.w);
    u.x = *(uint32_t*)&a;
    u.y = *(uint32_t*)&b;
    return u;
}

// ==================== fp16 GEMM, double-buffered w/ register prefetch ================
// 128x128 block, 8 warps of 32x64. A: [NN, LDA] fp16. W: [KTOT, ldw] fp32 @ncol0.
// D = A@W (fp32 accum). One __syncthreads per K-chunk; loads for chunk k+1 are in
// flight (registers) while chunk k's MMAs run; stores target the other smem buffer.
// Output: H16 ? g_h16[row] = half2(dis[row]*D) : C[row] = half2(op(D + bias))
template <int KTOT, int LDA, int LDC, bool TANH, bool HASB, bool H16>
__device__ __forceinline__ void gemm_mma(const __half* __restrict__ A,
                                         const float* __restrict__ W, int ldw,
                                         const float* __restrict__ bias,
                                         __half* __restrict__ C,
                                         int row0, int ncol0) {
    constexpr int CH = KTOT / 32;
    __shared__ __align__(16) uint16_t sA[2][128 * 40];   // stride 40 halves
    __shared__ __align__(16) uint16_t sB[2][32 * 136];   // stride 136 halves

    int tid = threadIdx.x, lane = tid & 31, wid = tid >> 5;
    int wm = wid & 3, wn = wid >> 2;  // warp tile: rows [wm*32,+32), cols [wn*64,+64)

    float acc[2][8][4];
    #pragma unroll
    for (int i = 0; i < 2; i++)
        #pragma unroll
        for (int j = 0; j < 8; j++)
            #pragma unroll
            for (int k = 0; k < 4; k++) acc[i][j][k] = 0.f;

    uint32_t aA = smem_u32(sA), aB = smem_u32(sB);
    uint32_t offA0 = (uint32_t)(((wm * 32 + (lane & 15)) * 40 + ((lane >> 4) << 3)) * 2);
    uint32_t offB0 = (uint32_t)(((lane & 15) * 136 + wn * 64 + ((lane >> 4) << 3)) * 2);

    // per-thread staging coordinates
    int ar0 = tid >> 2,        ac0 = (tid & 3) * 8;         // A slot 0
    int ar1 = (tid + 256) >> 2, ac1 = ((tid + 256) & 3) * 8; // A slot 1
    auto loadA = [&](int ch, uint4* areg) {
        int g0 = row0 + ar0, g1 = row0 + ar1;
        areg[0] = (g0 < NN) ? *(const uint4*)(A + (size_t)g0 * LDA + ch * 32 + ac0)
                            : make_uint4(0u, 0u, 0u, 0u);
        areg[1] = (g1 < NN) ? *(const uint4*)(A + (size_t)g1 * LDA + ch * 32 + ac1)
                            : make_uint4(0u, 0u, 0u, 0u);
    };
    auto storeA = [&](int buf, const uint4* areg) {
        *(uint4*)((char*)sA[buf] + (ar0 * 40 + ac0) * 2) = areg[0];
        *(uint4*)((char*)sA[buf] + (ar1 * 40 + ac1) * 2) = areg[1];
    };
    auto loadB = [&](int ch, float4* breg) {
        #pragma unroll
        for (int i = 0; i < 4; i++) {
            int lin = tid + 256 * i;
            int kr = lin >> 5, c4 = lin & 31;
            breg[i] = *(const float4*)(W + (size_t)(ch * 32 + kr) * ldw + ncol0 + c4 * 4);
        }
    };
    auto storeB = [&](int buf, const float4* breg) {
        #pragma unroll
        for (int i = 0; i < 4; i++) {
            int lin = tid + 256 * i;
            int kr = lin >> 5, c4 = lin & 31;
            *(uint2*)((char*)sB[buf] + (kr * 136 + c4 * 4) * 2) = pack4h(breg[i]);
        }
    };

    // prologue: chunk 0 -> buffer 0
    {
        uint4 a0[2];
        float4 b0[4];
        loadA(0, a0);
        loadB(0, b0);
        storeA(0, a0);
        storeB(0, b0);
    }

    for (int ch = 0; ch < CH; ch++) {
        int buf = ch & 1;
        bool more = (ch + 1 < CH);
        uint4 areg[2];
        float4 breg[4];
        if (more) { loadA(ch + 1, areg); loadB(ch + 1, breg); }  // in-flight during MMAs
        __syncthreads();  // buf's stores visible to all
        uint32_t bufA = aA + buf * 10240;
        uint32_t bufB = aB + buf * 8704;
        #pragma unroll
        for (int kb = 0; kb < 32; kb += 16) {
            uint32_t a[2][4], bb[4][4];
            #pragma unroll
            for (int mi = 0; mi < 2; mi++)
                ldmx4(a[mi], bufA + offA0 + (uint32_t)((mi * 16 * 40 + kb) * 2));
            #pragma unroll
            for (int g = 0; g < 4; g++)
                ldmx4t(bb[g], bufB + offB0 + (uint32_t)((kb * 136 + g * 16) * 2));
            #pragma unroll
            for (int mi = 0; mi < 2; mi++)
                #pragma unroll
                for (int g = 0; g < 4; g++) {
                    mma16816h(acc[mi][2 * g],     a[mi], &bb[g][0]);
                    mma16816h(acc[mi][2 * g + 1], a[mi], &bb[g][2]);
                }
        }
        // store chunk ch+1 into the other buffer; safe: that buffer's reads finished
        // before THIS iteration's __syncthreads (ldmatrix results land in registers).
        if (more) { storeA(buf ^ 1, areg); storeB(buf ^ 1, breg); }
    }
    __syncthreads();

    // ---- epilogue: half2 outputs
    int rbase = row0 + wm * 32 + (lane >> 2);
    #pragma unroll
    for (int mi = 0; mi < 2; mi++)
        #pragma unroll
        for (int h = 0; h < 2; h++) {
            int gr = rbase + mi * 16 + h * 8;
            if (gr >= NN) continue;
            float dd = H16 ? g_dis[gr] : 1.f;
            #pragma unroll
            for (int ni = 0; ni < 8; ni++) {
                int cl = wn * 64 + ni * 8 + (lane & 3) * 2;
                float v0 = acc[mi][ni][2 * h];
                float v1 = acc[mi][ni][2 * h + 1];
                if (HASB) { v0 += bias[cl]; v1 += bias[cl + 1]; }
                if (TANH) { v0 = tanhf(v0); v1 = tanhf(v1); }
                if (H16) {
                    ((__half2*)g_h16)[(size_t)gr * 64 + (cl >> 1)] =
                        __floats2half2_rn(dd * v0, dd * v1);
                } else {
                    *(__half2*)(C + (size_t)gr * LDC + cl) = __floats2half2_rn(v0, v1);
                }
            }
        }
}

__global__ void __launch_bounds__(256, 2) gemm_zc_mma(const float* __restrict__ Wz,
                                                      const float* __restrict__ bz,
                                                      const float* __restrict__ Wc,
                                                      const float* __restrict__ bc) {
    int conv = blockIdx.z;
    int nb = blockIdx.y * 128;
    const float* W = conv ? Wc : Wz;
    const float* b = conv ? bc : bz;
    gemm_mma<128, 256, 512, true, true, false>(
        (const __half*)g_xagg16 + conv * 128, W, 256, b + nb,
        (__half*)g_act16 + conv * 256 + nb, blockIdx.x * 128, nb);
}

__global__ void __launch_bounds__(256, 2) gemm_o_mma(const float* __restrict__ Wo) {
    gemm_mma<512, 512, 128, false, false, true>(
        (const __half*)g_act16, Wo, 128, nullptr, nullptr, blockIdx.x * 128, 0);
}

// ---------------- fused dtype detect + degree init ----------------
__global__ void detect_init_kernel(const unsigned int* __restrict__ w) {
    int i = blockIdx.x * blockDim.x + threadIdx.x;
    if (i < NN) g_deg[i] = 1;  // self loop pre-counted
    if (blockIdx.x == 0) {
        // If int64 (LE), high word of every value (<100000) is 0; sample 2048.
        int bad = 0;
        for (int k = threadIdx.x; k < 2048; k += blockDim.x)
            if (w[2 * k + 1] != 0u) bad = 1;
        if (__syncthreads_or(bad)) {
            if (threadIdx.x == 0) g_is64 = 0;
        } else {
            if (threadIdx.x == 0) g_is64 = 1;
        }
    }
}

// ---------------- degree count (4 edges/thread, vectorized decode) -----------
__global__ void count_kernel(const void* __restrict__ ei) {
    int e4 = blockIdx.x * blockDim.x + threadIdx.x;  // quad index
    if (e4 >= EE / 4) return;
    int d0, d1, d2, d3;
    if (g_is64) {
        const longlong2* pd = (const longlong2*)((const long long*)ei + EE);
        longlong2 v0 = pd[2 * e4];
        longlong2 v1 = pd[2 * e4 + 1];
        d0 = (int)v0.x; d1 = (int)v0.y; d2 = (int)v1.x; d3 = (int)v1.y;
    } else {
        const int4* pd = (const int4*)((const int*)ei + EE);
        int4 v = pd[e4];
        d0 = v.x; d1 = v.y; d2 = v.z; d3 = v.w;
    }
    atomicAdd(&g_deg[d0], 1);
    atomicAdd(&g_deg[d1], 1);
    atomicAdd(&g_deg[d2], 1);
    atomicAdd(&g_deg[d3], 1);
}

__global__ void scan1_kernel() {
    __shared__ int sh[1024];
    int i = blockIdx.x * 1024 + threadIdx.x;
    int v = 0;
    if (i < NN) {
        int d = g_deg[i];
        g_dis[i] = rsqrtf((float)d);
        v = d - 1;
    }
    sh[threadIdx.x] = v;
    __syncthreads();
    for (int ofs = 1; ofs < 1024; ofs <<= 1) {
        int t = 0;
        if ((int)threadIdx.x >= ofs) t = sh[threadIdx.x - ofs];
        __syncthreads();
        sh[threadIdx.x] += t;
        __syncthreads();
    }
    int incl = sh[threadIdx.x];
    if (i < NN) g_off[i] = incl - v;  // exclusive within block
    if (threadIdx.x == 1023) g_bsum[blockIdx.x] = incl;
}

// scan3 with scan2 folded in: every block redundantly scans the 98 block sums.
__global__ void scan3_kernel() {
    __shared__ int sh[128];
    int t = threadIdx.x;
    if (t < 128) {
        int v = (t < NB) ? g_bsum[t] : 0;
        sh[t] = v;
        __syncthreads();
        for (int ofs = 1; ofs < 128; ofs <<= 1) {
            int u = (t >= ofs) ? sh[t - ofs] : 0;
            __syncthreads();
            sh[t] += u;
            __syncthreads();
        }
        if (t < 128) sh[t] -= v;  // exclusive
    } else {
        for (int ofs = 1; ofs < 128; ofs <<= 1) { __syncthreads(); __syncthreads(); }
    }
    __syncthreads();
    int base = sh[blockIdx.x];
    int i = blockIdx.x * 1024 + t;
    if (i < NN) {
        int o = g_off[i] + base;
        g_off[i] = o;
        g_cur[i] = o;
    }
    if (i == 0) g_off[NN] = EE;
}

// ---------------- fused scatter (CSR fill, 2 edges/thread) + cast (uint4/thread)
__global__ void __launch_bounds__(256) scatter_cast_kernel(
        const void* __restrict__ ei,
        const float* __restrict__ lat, const float* __restrict__ cond) {
    int b = blockIdx.x;
    if (b < SCAT_BLOCKS) {
        int e2 = b * 256 + threadIdx.x;  // pair index
        if (e2 >= EE / 2) return;
        int s0, s1, d0, d1;
        if (g_is64) {
            const longlong2* ps = (const longlong2*)ei;
            const longlong2* pd = (const longlong2*)((const long long*)ei + EE);
            longlong2 sv = ps[e2];
            longlong2 dv = pd[e2];
            s0 = (int)sv.x; s1 = (int)sv.y;
            d0 = (int)dv.x; d1 = (int)dv.y;
        } else {
            const int2* ps = (const int2*)ei;
            const int2* pd = (const int2*)((const int*)ei + EE);
            int2 sv = ps[e2];
            int2 dv = pd[e2];
            s0 = sv.x; s1 = sv.y;
            d0 = dv.x; d1 = dv.y;
        }
        g_srcs[atomicAdd(&g_cur[d0], 1)] = s0;
        g_srcs[atomicAdd(&g_cur[d1], 1)] = s1;
    } else {
        int t = (b - SCAT_BLOCKS) * 256 + threadIdx.x;  // over NN*32 uint4 slots
        if (t >= NN * 32) return;
        int node = t >> 5;
        int c8 = t & 31;   // which 8-half group of the 256-wide row
        float dd = g_dis[node];
        const float4* src = (c8 < 16)
            ? ((const float4*)lat  + (size_t)node * 32 + 2 * c8)
            : ((const float4*)cond + (size_t)node * 32 + 2 * (c8 - 16));
        float4 v0 = src[0];
        float4 v1 = src[1];
        uint4 o;
        __half2* oh = (__half2*)&o;
        oh[0] = __floats2half2_rn(dd * v0.x, dd * v0.y);
        oh[1] = __floats2half2_rn(dd * v0.z, dd * v0.w);
        oh[2] = __floats2half2_rn(dd * v1.x, dd * v1.y);
        oh[3] = __floats2half2_rn(dd * v1.z, dd * v1.w);
        g_x16[(size_t)node * 32 + c8] = o;
    }
}

// ---------------- unpack-accumulate helpers ----------------
__device__ __forceinline__ void acc8(float* a, uint4 v) {
    const __half2* h = (const __half2*)&v;
    #pragma unroll
    for (int k = 0; k < 4; k++) {
        float2 f = __half22float2(h[k]);
        a[2 * k] += f.x;
        a[2 * k + 1] += f.y;
    }
}
__device__ __forceinline__ void acc4(float* a, uint2 v) {
    const __half2* h = (const __half2*)&v;
    float2 f0 = __half22float2(h[0]);
    float2 f1 = __half22float2(h[1]);
    a[0] += f0.x; a[1] += f0.y; a[2] += f1.x; a[3] += f1.y;
}

// ---------------- aggregation 1: fp16 gather, 512B/node, warp-per-node -----
__global__ void __launch_bounds__(256) aggx_kernel() {
    int gw = (int)((blockIdx.x * blockDim.x + threadIdx.x) >> 5);
    int lane = threadIdx.x & 31;
    if (gw >= NN) return;
    float dd = g_dis[gw];
    float a[8];
    #pragma unroll
    for (int k = 0; k < 8; k++) a[k] = 0.f;
    acc8(a, g_x16[(size_t)gw * 32 + lane]);  // self term (pre-scaled by dis)
    int beg = g_off[gw], end = g_off[gw + 1];
    #pragma unroll 4
    for (int j = beg; j < end; ++j) {
        int s = g_srcs[j];
        acc8(a, g_x16[(size_t)s * 32 + lane]);
    }
    uint4 o;
    __half2* oh = (__half2*)&o;
    #pragma unroll
    for (int k = 0; k < 4; k++)
        oh[k] = __floats2half2_rn(dd * a[2 * k], dd * a[2 * k + 1]);
    g_xagg16[(size_t)gw * 32 + lane] = o;
}

// ---------------- aggregation 2: fp16 gather, 256B/node, warp-per-node -----
__global__ void __launch_bounds__(256) agg2_kernel(const float* __restrict__ bo,
                                                   float* __restrict__ out) {
    int gw = (int)((blockIdx.x * blockDim.x + threadIdx.x) >> 5);
    int lane = threadIdx.x & 31;
    if (gw >= NN) return;
    float dd = g_dis[gw];
    float a[4];
    #pragma unroll
    for (int k = 0; k < 4; k++) a[k] = 0.f;
    acc4(a, g_h16[(size_t)gw * 32 + lane]);  // self term
    int beg = g_off[gw], end = g_off[gw + 1];
    #pragma unroll 4
    for (int j = beg; j < end; ++j) {
        int s = g_srcs[j];
        acc4(a, g_h16[(size_t)s * 32 + lane]);
    }
    float4 b = ((const float4*)bo)[lane];
    ((float4*)out)[(size_t)gw * 32 + lane] =
        make_float4(dd * a[0] + b.x, dd * a[1] + b.y, dd * a[2] + b.z, dd * a[3] + b.w);
}

// ---------------- launch ----------------
extern "C" void kernel_launch(void* const* d_in, const int* in_sizes, int n_in,
                              void* d_out, int out_size) {
    const float* latent    = (const float*)d_in[0];
    const float* condition = (const float*)d_in[1];
    const void*  ei        = d_in[2];
    const float* Wz = (const float*)d_in[3];
    const float* bz = (const float*)d_in[4];
    const float* Wc = (const float*)d_in[5];
    const float* bc = (const float*)d_in[6];
    const float* Wo = (const float*)d_in[7];
    const float* bo = (const float*)d_in[8];
    float* out = (float*)d_out;

    detect_init_kernel<<<(NN + 255) / 256, 256>>>((const unsigned int*)ei);
    count_kernel<<<(EE / 4 + 255) / 256, 256>>>(ei);
    scan1_kernel<<<NB, 1024>>>();
    scan3_kernel<<<NB, 1024>>>();
    scatter_cast_kernel<<<SCAT_BLOCKS + CAST_BLOCKS, 256>>>(ei, latent, condition);
    aggx_kernel<<<(NN * 32 + 255) / 256, 256>>>();

    int ntiles = (NN + 127) / 128;  // 782
    gemm_zc_mma<<<dim3(ntiles, 2, 2), 256>>>(Wz, bz, Wc, bc);
    gemm_o_mma<<<ntiles, 256>>>(Wo);

    agg2_kernel<<<(NN * 32 + 255) / 256, 256>>>(bo, out);
}

// round 15
// speedup vs baseline: 1.4347x; 1.0206x over previous
#include <cuda_runtime.h>
#include <cuda_bf16.h>
#include <cuda_fp16.h>
#include <cstdint>
#include <math.h>

#define NN 100000
#define EE 3200000
#define NB 98  // ceil(NN/1024)

#define SCAT_BLOCKS ((EE / 2 + 255) / 256)   // 6250  (2 edges per thread)
#define CAST_BLOCKS ((NN * 32 + 255) / 256)  // 12500 (uint4 per thread)

// ---------------- device scratch (static, no runtime alloc) ----------------
__device__ int   g_is64;
__device__ int   g_deg[NN];
__device__ float g_dis[NN];
__device__ int   g_off[NN + 1];
__device__ int   g_cur[NN];
__device__ int   g_bsum[NB];
__device__ int   g_srcs[EE];                       // CSR-sorted src per dst
__device__ uint4 g_x16   [(size_t)NN * 32];        // fp16 dis-scaled [latent|cond]
__device__ uint4 g_xagg16[(size_t)NN * 32];        // fp16 aggregated features (256)
__device__ uint4 g_act16 [(size_t)NN * 64];        // fp16 tanh activations (512)
__device__ uint2 g_h16   [(size_t)NN * 32];        // fp16 dis-scaled h2 (128)

// ==================== warp-MMA helpers (sm_80+ HMMA path) ====================
__device__ __forceinline__ uint32_t smem_u32(const void* p) {
    uint32_t a;
    asm("{ .reg .u64 t; cvta.to.shared.u64 t, %1; cvt.u32.u64 %0, t; }" : "=r"(a) : "l"(p));
    return a;
}

// fp16 x fp16 -> fp32 accumulate
__device__ __forceinline__ void mma16816h(float* d, const uint32_t* a, const uint32_t* b) {
    asm volatile(
        "mma.sync.aligned.m16n8k16.row.col.f32.f16.f16.f32 "
        "{%0,%1,%2,%3}, {%4,%5,%6,%7}, {%8,%9}, {%0,%1,%2,%3};"
        : "+f"(d[0]), "+f"(d[1]), "+f"(d[2]), "+f"(d[3])
        : "r"(a[0]), "r"(a[1]), "r"(a[2]), "r"(a[3]), "r"(b[0]), "r"(b[1]));
}

__device__ __forceinline__ void ldmx4(uint32_t* r, uint32_t addr) {
    asm volatile("ldmatrix.sync.aligned.m8n8.x4.shared.b16 {%0,%1,%2,%3}, [%4];"
                 : "=r"(r[0]), "=r"(r[1]), "=r"(r[2]), "=r"(r[3]) : "r"(addr));
}
__device__ __forceinline__ void ldmx4t(uint32_t* r, uint32_t addr) {
    asm volatile("ldmatrix.sync.aligned.m8n8.x4.trans.shared.b16 {%0,%1,%2,%3}, [%4];"
                 : "=r"(r[0]), "=r"(r[1]), "=r"(r[2]), "=r"(r[3]) : "r"(addr));
}

// pack fp32x4 -> fp16x4 (round-to-nearest)
__device__ __forceinline__ uint2 pack4h(float4 v) {
    uint2 u;
    __half2 a = __floats2half2_rn(v.x, v.y);
    __half2 b = __floats2half2_rn(v.z, v.w);
    u.x = *(uint32_t*)&a;
    u.y = *(uint32_t*)&b;
    return u;
}

// smem layout inside the single dynamic-free static block:
//   [0, 10240)      sA buf0   [10240, 20480) sA buf1   (128 rows x 40 halves)
//   [20480, 29184)  sB buf0   [29184, 37888) sB buf1   (32 rows x 136 halves)
// Epilogue reuses the whole block as 8 warp patches of 32x72 halves (4608B each).
#define SMEM_BYTES 37888
#define SB_OFF 20480
#define PATCH_STRIDE 4608

// ==================== fp16 GEMM, double-buffered w/ register prefetch ================
// 128x128 block, 8 warps of 32x64. A: [NN, LDA] fp16. W: [KTOT, ldw] fp32 @ncol0.
// D = A@W (fp32 accum). Epilogue: smem-transpose per warp -> fully coalesced
// 128B row stores (same __floats2half2_rn values; bitwise identical output).
// Output: H16 ? g_h16[row] = half2(dis[row]*D) : C[row] = half2(op(D + bias))
template <int KTOT, int LDA, int LDC, bool TANH, bool HASB, bool H16>
__device__ __forceinline__ void gemm_mma(const __half* __restrict__ A,
                                         const float* __restrict__ W, int ldw,
                                         const float* __restrict__ bias,
                                         __half* __restrict__ C,
                                         int row0, int ncol0) {
    constexpr int CH = KTOT / 32;
    __shared__ __align__(16) char smemblk[SMEM_BYTES];

    int tid = threadIdx.x, lane = tid & 31, wid = tid >> 5;
    int wm = wid & 3, wn = wid >> 2;  // warp tile: rows [wm*32,+32), cols [wn*64,+64)

    float acc[2][8][4];
    #pragma unroll
    for (int i = 0; i < 2; i++)
        #pragma unroll
        for (int j = 0; j < 8; j++)
            #pragma unroll
            for (int k = 0; k < 4; k++) acc[i][j][k] = 0.f;

    uint32_t base = smem_u32(smemblk);
    uint32_t aA = base, aB = base + SB_OFF;
    uint32_t offA0 = (uint32_t)(((wm * 32 + (lane & 15)) * 40 + ((lane >> 4) << 3)) * 2);
    uint32_t offB0 = (uint32_t)(((lane & 15) * 136 + wn * 64 + ((lane >> 4) << 3)) * 2);

    // per-thread staging coordinates
    int ar0 = tid >> 2,        ac0 = (tid & 3) * 8;         // A slot 0
    int ar1 = (tid + 256) >> 2, ac1 = ((tid + 256) & 3) * 8; // A slot 1
    auto loadA = [&](int ch, uint4* areg) {
        int g0 = row0 + ar0, g1 = row0 + ar1;
        areg[0] = (g0 < NN) ? *(const uint4*)(A + (size_t)g0 * LDA + ch * 32 + ac0)
                            : make_uint4(0u, 0u, 0u, 0u);
        areg[1] = (g1 < NN) ? *(const uint4*)(A + (size_t)g1 * LDA + ch * 32 + ac1)
                            : make_uint4(0u, 0u, 0u, 0u);
    };
    auto storeA = [&](int buf, const uint4* areg) {
        *(uint4*)(smemblk + buf * 10240 + (ar0 * 40 + ac0) * 2) = areg[0];
        *(uint4*)(smemblk + buf * 10240 + (ar1 * 40 + ac1) * 2) = areg[1];
    };
    auto loadB = [&](int ch, float4* breg) {
        #pragma unroll
        for (int i = 0; i < 4; i++) {
            int lin = tid + 256 * i;
            int kr = lin >> 5, c4 = lin & 31;
            breg[i] = *(const float4*)(W + (size_t)(ch * 32 + kr) * ldw + ncol0 + c4 * 4);
        }
    };
    auto storeB = [&](int buf, const float4* breg) {
        #pragma unroll
        for (int i = 0; i < 4; i++) {
            int lin = tid + 256 * i;
            int kr = lin >> 5, c4 = lin & 31;
            *(uint2*)(smemblk + SB_OFF + buf * 8704 + (kr * 136 + c4 * 4) * 2) =
                pack4h(breg[i]);
        }
    };

    // prologue: chunk 0 -> buffer 0
    {
        uint4 a0[2];
        float4 b0[4];
        loadA(0, a0);
        loadB(0, b0);
        storeA(0, a0);
        storeB(0, b0);
    }

    for (int ch = 0; ch < CH; ch++) {
        int buf = ch & 1;
        bool more = (ch + 1 < CH);
        uint4 areg[2];
        float4 breg[4];
        if (more) { loadA(ch + 1, areg); loadB(ch + 1, breg); }  // in-flight during MMAs
        __syncthreads();  // buf's stores visible to all
        uint32_t bufA = aA + buf * 10240;
        uint32_t bufB = aB + buf * 8704;
        #pragma unroll
        for (int kb = 0; kb < 32; kb += 16) {
            uint32_t a[2][4], bb[4][4];
            #pragma unroll
            for (int mi = 0; mi < 2; mi++)
                ldmx4(a[mi], bufA + offA0 + (uint32_t)((mi * 16 * 40 + kb) * 2));
            #pragma unroll
            for (int g = 0; g < 4; g++)
                ldmx4t(bb[g], bufB + offB0 + (uint32_t)((kb * 136 + g * 16) * 2));
            #pragma unroll
            for (int mi = 0; mi < 2; mi++)
                #pragma unroll
                for (int g = 0; g < 4; g++) {
                    mma16816h(acc[mi][2 * g],     a[mi], &bb[g][0]);
                    mma16816h(acc[mi][2 * g + 1], a[mi], &bb[g][2]);
                }
        }
        // store chunk ch+1 into the other buffer; safe: that buffer's reads finished
        // before THIS iteration's __syncthreads (ldmatrix results land in registers).
        if (more) { storeA(buf ^ 1, areg); storeB(buf ^ 1, breg); }
    }
    __syncthreads();  // mainloop smem reads done -> safe to reuse as patches

    // ---- epilogue phase 1: stage warp's 32x64 fp16 tile into its smem patch
    char* patch = smemblk + wid * PATCH_STRIDE;  // [32][72] halves, stride 144B
    #pragma unroll
    for (int mi = 0; mi < 2; mi++)
        #pragma unroll
        for (int h = 0; h < 2; h++) {
            int lr = mi * 16 + h * 8 + (lane >> 2);
            int gr = row0 + wm * 32 + lr;
            float dd = (H16 && gr < NN) ? g_dis[gr] : 1.f;
            #pragma unroll
            for (int ni = 0; ni < 8; ni++) {
                int lc = ni * 8 + (lane & 3) * 2;
                int cl = wn * 64 + lc;
                float v0 = acc[mi][ni][2 * h];
                float v1 = acc[mi][ni][2 * h + 1];
                if (HASB) { v0 += bias[cl]; v1 += bias[cl + 1]; }
                if (TANH) { v0 = tanhf(v0); v1 = tanhf(v1); }
                __half2 p = H16 ? __floats2half2_rn(dd * v0, dd * v1)
                                : __floats2half2_rn(v0, v1);
                *(__half2*)(patch + (lr * 72 + lc) * 2) = p;
            }
        }
    __syncwarp();

    // ---- epilogue phase 2: coalesced 128B row stores (8 lanes x 16B per row)
    __half* dstbase = H16 ? (__half*)g_h16 : C;
    int ldc = H16 ? 128 : LDC;
    #pragma unroll
    for (int rg = 0; rg < 8; rg++) {
        int lr = rg * 4 + (lane >> 3);   // 4 rows per iteration
        int seg = lane & 7;              // 8 segments of 8 halves
        int gr = row0 + wm * 32 + lr;
        uint4 v = *(uint4*)(patch + (lr * 72 + seg * 8) * 2);
        if (gr < NN)
            *(uint4*)(dstbase + (size_t)gr * ldc + wn * 64 + seg * 8) = v;
    }
}

__global__ void __launch_bounds__(256, 2) gemm_zc_mma(const float* __restrict__ Wz,
                                                      const float* __restrict__ bz,
                                                      const float* __restrict__ Wc,
                                                      const float* __restrict__ bc) {
    int conv = blockIdx.z;
    int nb = blockIdx.y * 128;
    const float* W = conv ? Wc : Wz;
    const float* b = conv ? bc : bz;
    gemm_mma<128, 256, 512, true, true, false>(
        (const __half*)g_xagg16 + conv * 128, W, 256, b + nb,
        (__half*)g_act16 + conv * 256 + nb, blockIdx.x * 128, nb);
}

__global__ void __launch_bounds__(256, 2) gemm_o_mma(const float* __restrict__ Wo) {
    gemm_mma<512, 512, 128, false, false, true>(
        (const __half*)g_act16, Wo, 128, nullptr, nullptr, blockIdx.x * 128, 0);
}

// ---------------- fused dtype detect + degree init ----------------
__global__ void detect_init_kernel(const unsigned int* __restrict__ w) {
    int i = blockIdx.x * blockDim.x + threadIdx.x;
    if (i < NN) g_deg[i] = 1;  // self loop pre-counted
    if (blockIdx.x == 0) {
        // If int64 (LE), high word of every value (<100000) is 0; sample 2048.
        int bad = 0;
        for (int k = threadIdx.x; k < 2048; k += blockDim.x)
            if (w[2 * k + 1] != 0u) bad = 1;
        if (__syncthreads_or(bad)) {
            if (threadIdx.x == 0) g_is64 = 0;
        } else {
            if (threadIdx.x == 0) g_is64 = 1;
        }
    }
}

// ---------------- degree count (4 edges/thread, vectorized decode) -----------
__global__ void count_kernel(const void* __restrict__ ei) {
    int e4 = blockIdx.x * blockDim.x + threadIdx.x;  // quad index
    if (e4 >= EE / 4) return;
    int d0, d1, d2, d3;
    if (g_is64) {
        const longlong2* pd = (const longlong2*)((const long long*)ei + EE);
        longlong2 v0 = pd[2 * e4];
        longlong2 v1 = pd[2 * e4 + 1];
        d0 = (int)v0.x; d1 = (int)v0.y; d2 = (int)v1.x; d3 = (int)v1.y;
    } else {
        const int4* pd = (const int4*)((const int*)ei + EE);
        int4 v = pd[e4];
        d0 = v.x; d1 = v.y; d2 = v.z; d3 = v.w;
    }
    atomicAdd(&g_deg[d0], 1);
    atomicAdd(&g_deg[d1], 1);
    atomicAdd(&g_deg[d2], 1);
    atomicAdd(&g_deg[d3], 1);
}

__global__ void scan1_kernel() {
    __shared__ int sh[1024];
    int i = blockIdx.x * 1024 + threadIdx.x;
    int v = 0;
    if (i < NN) {
        int d = g_deg[i];
        g_dis[i] = rsqrtf((float)d);
        v = d - 1;
    }
    sh[threadIdx.x] = v;
    __syncthreads();
    for (int ofs = 1; ofs < 1024; ofs <<= 1) {
        int t = 0;
        if ((int)threadIdx.x >= ofs) t = sh[threadIdx.x - ofs];
        __syncthreads();
        sh[threadIdx.x] += t;
        __syncthreads();
    }
    int incl = sh[threadIdx.x];
    if (i < NN) g_off[i] = incl - v;  // exclusive within block
    if (threadIdx.x == 1023) g_bsum[blockIdx.x] = incl;
}

// scan3 with scan2 folded in: every block redundantly scans the 98 block sums.
__global__ void scan3_kernel() {
    __shared__ int sh[128];
    int t = threadIdx.x;
    if (t < 128) {
        int v = (t < NB) ? g_bsum[t] : 0;
        sh[t] = v;
        __syncthreads();
        for (int ofs = 1; ofs < 128; ofs <<= 1) {
            int u = (t >= ofs) ? sh[t - ofs] : 0;
            __syncthreads();
            sh[t] += u;
            __syncthreads();
        }
        if (t < 128) sh[t] -= v;  // exclusive
    } else {
        for (int ofs = 1; ofs < 128; ofs <<= 1) { __syncthreads(); __syncthreads(); }
    }
    __syncthreads();
    int base = sh[blockIdx.x];
    int i = blockIdx.x * 1024 + t;
    if (i < NN) {
        int o = g_off[i] + base;
        g_off[i] = o;
        g_cur[i] = o;
    }
    if (i == 0) g_off[NN] = EE;
}

// ---------------- fused scatter (CSR fill, 2 edges/thread) + cast (uint4/thread)
__global__ void __launch_bounds__(256) scatter_cast_kernel(
        const void* __restrict__ ei,
        const float* __restrict__ lat, const float* __restrict__ cond) {
    int b = blockIdx.x;
    if (b < SCAT_BLOCKS) {
        int e2 = b * 256 + threadIdx.x;  // pair index
        if (e2 >= EE / 2) return;
        int s0, s1, d0, d1;
        if (g_is64) {
            const longlong2* ps = (const longlong2*)ei;
            const longlong2* pd = (const longlong2*)((const long long*)ei + EE);
            longlong2 sv = ps[e2];
            longlong2 dv = pd[e2];
            s0 = (int)sv.x; s1 = (int)sv.y;
            d0 = (int)dv.x; d1 = (int)dv.y;
        } else {
            const int2* ps = (const int2*)ei;
            const int2* pd = (const int2*)((const int*)ei + EE);
            int2 sv = ps[e2];
            int2 dv = pd[e2];
            s0 = sv.x; s1 = sv.y;
            d0 = dv.x; d1 = dv.y;
        }
        g_srcs[atomicAdd(&g_cur[d0], 1)] = s0;
        g_srcs[atomicAdd(&g_cur[d1], 1)] = s1;
    } else {
        int t = (b - SCAT_BLOCKS) * 256 + threadIdx.x;  // over NN*32 uint4 slots
        if (t >= NN * 32) return;
        int node = t >> 5;
        int c8 = t & 31;   // which 8-half group of the 256-wide row
        float dd = g_dis[node];
        const float4* src = (c8 < 16)
            ? ((const float4*)lat  + (size_t)node * 32 + 2 * c8)
            : ((const float4*)cond + (size_t)node * 32 + 2 * (c8 - 16));
        float4 v0 = src[0];
        float4 v1 = src[1];
        uint4 o;
        __half2* oh = (__half2*)&o;
        oh[0] = __floats2half2_rn(dd * v0.x, dd * v0.y);
        oh[1] = __floats2half2_rn(dd * v0.z, dd * v0.w);
        oh[2] = __floats2half2_rn(dd * v1.x, dd * v1.y);
        oh[3] = __floats2half2_rn(dd * v1.z, dd * v1.w);
        g_x16[(size_t)node * 32 + c8] = o;
    }
}

// ---------------- unpack-accumulate helpers ----------------
__device__ __forceinline__ void acc8(float* a, uint4 v) {
    const __half2* h = (const __half2*)&v;
    #pragma unroll
    for (int k = 0; k < 4; k++) {
        float2 f = __half22float2(h[k]);
        a[2 * k] += f.x;
        a[2 * k + 1] += f.y;
    }
}
__device__ __forceinline__ void acc4(float* a, uint2 v) {
    const __half2* h = (const __half2*)&v;
    float2 f0 = __half22float2(h[0]);
    float2 f1 = __half22float2(h[1]);
    a[0] += f0.x; a[1] += f0.y; a[2] += f1.x; a[3] += f1.y;
}

// ---------------- aggregation 1: fp16 gather, 512B/node, warp-per-node -----
__global__ void __launch_bounds__(256) aggx_kernel() {
    int gw = (int)((blockIdx.x * blockDim.x + threadIdx.x) >> 5);
    int lane = threadIdx.x & 31;
    if (gw >= NN) return;
    float dd = g_dis[gw];
    float a[8];
    #pragma unroll
    for (int k = 0; k < 8; k++) a[k] = 0.f;
    acc8(a, g_x16[(size_t)gw * 32 + lane]);  // self term (pre-scaled by dis)
    int beg = g_off[gw], end = g_off[gw + 1];
    #pragma unroll 8
    for (int j = beg; j < end; ++j) {
        int s = g_srcs[j];
        acc8(a, g_x16[(size_t)s * 32 + lane]);
    }
    uint4 o;
    __half2* oh = (__half2*)&o;
    #pragma unroll
    for (int k = 0; k < 4; k++)
        oh[k] = __floats2half2_rn(dd * a[2 * k], dd * a[2 * k + 1]);
    g_xagg16[(size_t)gw * 32 + lane] = o;
}

// ---------------- aggregation 2: fp16 gather, 256B/node, warp-per-node -----
__global__ void __launch_bounds__(256) agg2_kernel(const float* __restrict__ bo,
                                                   float* __restrict__ out) {
    int gw = (int)((blockIdx.x * blockDim.x + threadIdx.x) >> 5);
    int lane = threadIdx.x & 31;
    if (gw >= NN) return;
    float dd = g_dis[gw];
    float a[4];
    #pragma unroll
    for (int k = 0; k < 4; k++) a[k] = 0.f;
    acc4(a, g_h16[(size_t)gw * 32 + lane]);  // self term
    int beg = g_off[gw], end = g_off[gw + 1];
    #pragma unroll 8
    for (int j = beg; j < end; ++j) {
        int s = g_srcs[j];
        acc4(a, g_h16[(size_t)s * 32 + lane]);
    }
    float4 b = ((const float4*)bo)[lane];
    ((float4*)out)[(size_t)gw * 32 + lane] =
        make_float4(dd * a[0] + b.x, dd * a[1] + b.y, dd * a[2] + b.z, dd * a[3] + b.w);
}

// ---------------- launch ----------------
extern "C" void kernel_launch(void* const* d_in, const int* in_sizes, int n_in,
                              void* d_out, int out_size) {
    const float* latent    = (const float*)d_in[0];
    const float* condition = (const float*)d_in[1];
    const void*  ei        = d_in[2];
    const float* Wz = (const float*)d_in[3];
    const float* bz = (const float*)d_in[4];
    const float* Wc = (const float*)d_in[5];
    const float* bc = (const float*)d_in[6];
    const float* Wo = (const float*)d_in[7];
    const float* bo = (const float*)d_in[8];
    float* out = (float*)d_out;

    detect_init_kernel<<<(NN + 255) / 256, 256>>>((const unsigned int*)ei);
    count_kernel<<<(EE / 4 + 255) / 256, 256>>>(ei);
    scan1_kernel<<<NB, 1024>>>();
    scan3_kernel<<<NB, 1024>>>();
    scatter_cast_kernel<<<SCAT_BLOCKS + CAST_BLOCKS, 256>>>(ei, latent, condition);
    aggx_kernel<<<(NN * 32 + 255) / 256, 256>>>();

    int ntiles = (NN + 127) / 128;  // 782
    gemm_zc_mma<<<dim3(ntiles, 2, 2), 256>>>(Wz, bz, Wc, bc);
    gemm_o_mma<<<ntiles, 256>>>(Wo);

    agg2_kernel<<<(NN * 32 + 255) / 256, 256>>>(bo, out);
}

// round 16
// speedup vs baseline: 1.4877x; 1.0370x over previous
#include <cuda_runtime.h>
#include <cuda_bf16.h>
#include <cuda_fp16.h>
#include <cstdint>
#include <math.h>

#define NN 100000
#define EE 3200000
#define NB 98  // ceil(NN/1024)

#define SCAT_BLOCKS ((EE / 2 + 255) / 256)   // 6250  (2 edges per thread)
#define CAST_BLOCKS ((NN * 32 + 255) / 256)  // 12500 (uint4 per thread)

#define ZC_TILES 782   // ceil(NN/128)
#define ZC_CTAX  74    // 74*2*2 = 296 CTAs = one full wave at occ 2

// ---------------- device scratch (static, no runtime alloc) ----------------
__device__ int   g_is64;
__device__ int   g_deg[NN];
__device__ float g_dis[NN];
__device__ int   g_off[NN + 1];
__device__ int   g_cur[NN];
__device__ int   g_bsum[NB];
__device__ int   g_srcs[EE];                       // CSR-sorted src per dst
__device__ uint4 g_x16   [(size_t)NN * 32];        // fp16 dis-scaled [latent|cond]
__device__ uint4 g_xagg16[(size_t)NN * 32];        // fp16 aggregated features (256)
__device__ uint4 g_act16 [(size_t)NN * 64];        // fp16 tanh activations (512)
__device__ uint2 g_h16   [(size_t)NN * 32];        // fp16 dis-scaled h2 (128)

// ==================== warp-MMA helpers (sm_80+ HMMA path) ====================
__device__ __forceinline__ uint32_t smem_u32(const void* p) {
    uint32_t a;
    asm("{ .reg .u64 t; cvta.to.shared.u64 t, %1; cvt.u32.u64 %0, t; }" : "=r"(a) : "l"(p));
    return a;
}

// fp16 x fp16 -> fp32 accumulate
__device__ __forceinline__ void mma16816h(float* d, const uint32_t* a, const uint32_t* b) {
    asm volatile(
        "mma.sync.aligned.m16n8k16.row.col.f32.f16.f16.f32 "
        "{%0,%1,%2,%3}, {%4,%5,%6,%7}, {%8,%9}, {%0,%1,%2,%3};"
        : "+f"(d[0]), "+f"(d[1]), "+f"(d[2]), "+f"(d[3])
        : "r"(a[0]), "r"(a[1]), "r"(a[2]), "r"(a[3]), "r"(b[0]), "r"(b[1]));
}

__device__ __forceinline__ void ldmx4(uint32_t* r, uint32_t addr) {
    asm volatile("ldmatrix.sync.aligned.m8n8.x4.shared.b16 {%0,%1,%2,%3}, [%4];"
                 : "=r"(r[0]), "=r"(r[1]), "=r"(r[2]), "=r"(r[3]) : "r"(addr));
}
__device__ __forceinline__ void ldmx4t(uint32_t* r, uint32_t addr) {
    asm volatile("ldmatrix.sync.aligned.m8n8.x4.trans.shared.b16 {%0,%1,%2,%3}, [%4];"
                 : "=r"(r[0]), "=r"(r[1]), "=r"(r[2]), "=r"(r[3]) : "r"(addr));
}

// pack fp32x4 -> fp16x4 (round-to-nearest)
__device__ __forceinline__ uint2 pack4h(float4 v) {
    uint2 u;
    __half2 a = __floats2half2_rn(v.x, v.y);
    __half2 b = __floats2half2_rn(v.z, v.w);
    u.x = *(uint32_t*)&a;
    u.y = *(uint32_t*)&b;
    return u;
}

// ==================== persistent zc GEMM: W resident in smem ====================
// Grid (74, 2, 2); each CTA: convert its 128x128 fp32 W slice to fp16 smem ONCE
// (same pack4h rounding as before -> bitwise-identical results), then loop row
// tiles with stride. A single-buffered but register-prefetched across chunks.
// smem: [0, 34816) W fp16 [128][136]; [34816, 45056) A [128][40] / epi patches.
__global__ void __launch_bounds__(256, 2) gemm_zc_mma(const float* __restrict__ Wz,
                                                      const float* __restrict__ bz,
                                                      const float* __restrict__ Wc,
                                                      const float* __restrict__ bc) {
    __shared__ __align__(16) char smemblk[45056];
    int conv = blockIdx.z;
    int nb = blockIdx.y * 128;
    const float* W = conv ? Wc : Wz;
    const float* bias = (conv ? bc : bz) + nb;
    const __half* A = (const __half*)g_xagg16 + conv * 128;
    __half* C = (__half*)g_act16 + conv * 256 + nb;

    int tid = threadIdx.x, lane = tid & 31, wid = tid >> 5;
    int wm = wid & 3, wn = wid >> 2;  // warp tile: rows [wm*32,+32), cols [wn*64,+64)

    // ---- stage W fp32 -> fp16 resident (128 rows x 128 cols, stride 136 halves)
    #pragma unroll
    for (int i = 0; i < 16; i++) {
        int lin = tid + 256 * i;   // 0..4095 float4 slots
        int kr = lin >> 5;         // K row 0..127
        int c4 = lin & 31;         // float4 column
        float4 v = *(const float4*)(W + (size_t)kr * 256 + nb + c4 * 4);
        *(uint2*)(smemblk + (kr * 136 + c4 * 4) * 2) = pack4h(v);
    }

    uint32_t base = smem_u32(smemblk);
    uint32_t aW = base;
    uint32_t aA = base + 34816;
    uint32_t offA0 = (uint32_t)(((wm * 32 + (lane & 15)) * 40 + ((lane >> 4) << 3)) * 2);
    uint32_t offB0 = (uint32_t)(((lane & 15) * 136 + wn * 64 + ((lane >> 4) << 3)) * 2);

    int ar0 = tid >> 2,         ac0 = (tid & 3) * 8;
    int ar1 = (tid + 256) >> 2, ac1 = ((tid + 256) & 3) * 8;

    for (int tile = blockIdx.x; tile < ZC_TILES; tile += ZC_CTAX) {
        int row0 = tile * 128;
        float acc[2][8][4];
        #pragma unroll
        for (int i = 0; i < 2; i++)
            #pragma unroll
            for (int j = 0; j < 8; j++)
                #pragma unroll
                for (int k = 0; k < 4; k++) acc[i][j][k] = 0.f;

        // preload chunk 0 A into registers
        uint4 areg[2];
        {
            int g0 = row0 + ar0, g1 = row0 + ar1;
            areg[0] = (g0 < NN) ? *(const uint4*)(A + (size_t)g0 * 256 + ac0)
                                : make_uint4(0u, 0u, 0u, 0u);
            areg[1] = (g1 < NN) ? *(const uint4*)(A + (size_t)g1 * 256 + ac1)
                                : make_uint4(0u, 0u, 0u, 0u);
        }
        #pragma unroll
        for (int ch = 0; ch < 4; ch++) {
            __syncthreads();  // prior smem reads (MMA/epilogue; or W stores 1st iter) done
            *(uint4*)(smemblk + 34816 + (ar0 * 40 + ac0) * 2) = areg[0];
            *(uint4*)(smemblk + 34816 + (ar1 * 40 + ac1) * 2) = areg[1];
            __syncthreads();  // A chunk visible
            if (ch < 3) {     // prefetch next chunk during MMAs
                int g0 = row0 + ar0, g1 = row0 + ar1;
                int kofs = (ch + 1) * 32;
                areg[0] = (g0 < NN) ? *(const uint4*)(A + (size_t)g0 * 256 + kofs + ac0)
                                    : make_uint4(0u, 0u, 0u, 0u);
                areg[1] = (g1 < NN) ? *(const uint4*)(A + (size_t)g1 * 256 + kofs + ac1)
                                    : make_uint4(0u, 0u, 0u, 0u);
            }
            #pragma unroll
            for (int kb = 0; kb < 32; kb += 16) {
                uint32_t a[2][4], bb[4][4];
                #pragma unroll
                for (int mi = 0; mi < 2; mi++)
                    ldmx4(a[mi], aA + offA0 + (uint32_t)((mi * 16 * 40 + kb) * 2));
                #pragma unroll
                for (int g = 0; g < 4; g++)
                    ldmx4t(bb[g], aW + offB0 +
                           (uint32_t)(((ch * 32 + kb) * 136 + g * 16) * 2));
                #pragma unroll
                for (int mi = 0; mi < 2; mi++)
                    #pragma unroll
                    for (int g = 0; g < 4; g++) {
                        mma16816h(acc[mi][2 * g],     a[mi], &bb[g][0]);
                        mma16816h(acc[mi][2 * g + 1], a[mi], &bb[g][2]);
                    }
            }
        }
        __syncthreads();  // MMA reads of A region done -> reuse as epilogue patches

        // ---- epilogue: 4 quarter-passes of 8 rows, coalesced 128B stores
        char* patch = smemblk + 34816 + wid * 1152;  // 8 rows x 72 halves
        #pragma unroll
        for (int qp = 0; qp < 4; qp++) {
            int mi = qp >> 1, h = qp & 1;
            int lr = lane >> 2;  // row 0..7 within pass
            #pragma unroll
            for (int ni = 0; ni < 8; ni++) {
                int lc = ni * 8 + (lane & 3) * 2;
                float v0 = acc[mi][ni][2 * h]     + bias[wn * 64 + lc];
                float v1 = acc[mi][ni][2 * h + 1] + bias[wn * 64 + lc + 1];
                v0 = tanhf(v0);
                v1 = tanhf(v1);
                *(__half2*)(patch + (lr * 72 + lc) * 2) = __floats2half2_rn(v0, v1);
            }
            __syncwarp();
            #pragma unroll
            for (int it = 0; it < 2; it++) {
                int lr2 = it * 4 + (lane >> 3);
                int seg = lane & 7;
                int gr = row0 + wm * 32 + qp * 8 + lr2;
                uint4 v = *(uint4*)(patch + (lr2 * 72 + seg * 8) * 2);
                if (gr < NN)
                    *(uint4*)(C + (size_t)gr * 512 + wn * 64 + seg * 8) = v;
            }
            __syncwarp();
        }
        // next tile's loop-top __syncthreads separates patch reads from A staging
    }
}

// smem layout for the unchanged o-GEMM template:
//   [0, 10240)      sA buf0   [10240, 20480) sA buf1   (128 rows x 40 halves)
//   [20480, 29184)  sB buf0   [29184, 37888) sB buf1   (32 rows x 136 halves)
// Epilogue reuses the whole block as 8 warp patches of 32x72 halves (4608B each).
#define SMEM_BYTES 37888
#define SB_OFF 20480
#define PATCH_STRIDE 4608

// ==================== fp16 GEMM (o), double-buffered w/ register prefetch ============
template <int KTOT, int LDA, int LDC, bool TANH, bool HASB, bool H16>
__device__ __forceinline__ void gemm_mma(const __half* __restrict__ A,
                                         const float* __restrict__ W, int ldw,
                                         const float* __restrict__ bias,
                                         __half* __restrict__ C,
                                         int row0, int ncol0) {
    constexpr int CH = KTOT / 32;
    __shared__ __align__(16) char smemblk[SMEM_BYTES];

    int tid = threadIdx.x, lane = tid & 31, wid = tid >> 5;
    int wm = wid & 3, wn = wid >> 2;

    float acc[2][8][4];
    #pragma unroll
    for (int i = 0; i < 2; i++)
        #pragma unroll
        for (int j = 0; j < 8; j++)
            #pragma unroll
            for (int k = 0; k < 4; k++) acc[i][j][k] = 0.f;

    uint32_t base = smem_u32(smemblk);
    uint32_t aA = base, aB = base + SB_OFF;
    uint32_t offA0 = (uint32_t)(((wm * 32 + (lane & 15)) * 40 + ((lane >> 4) << 3)) * 2);
    uint32_t offB0 = (uint32_t)(((lane & 15) * 136 + wn * 64 + ((lane >> 4) << 3)) * 2);

    int ar0 = tid >> 2,        ac0 = (tid & 3) * 8;
    int ar1 = (tid + 256) >> 2, ac1 = ((tid + 256) & 3) * 8;
    auto loadA = [&](int ch, uint4* areg) {
        int g0 = row0 + ar0, g1 = row0 + ar1;
        areg[0] = (g0 < NN) ? *(const uint4*)(A + (size_t)g0 * LDA + ch * 32 + ac0)
                            : make_uint4(0u, 0u, 0u, 0u);
        areg[1] = (g1 < NN) ? *(const uint4*)(A + (size_t)g1 * LDA + ch * 32 + ac1)
                            : make_uint4(0u, 0u, 0u, 0u);
    };
    auto storeA = [&](int buf, const uint4* areg) {
        *(uint4*)(smemblk + buf * 10240 + (ar0 * 40 + ac0) * 2) = areg[0];
        *(uint4*)(smemblk + buf * 10240 + (ar1 * 40 + ac1) * 2) = areg[1];
    };
    auto loadB = [&](int ch, float4* breg) {
        #pragma unroll
        for (int i = 0; i < 4; i++) {
            int lin = tid + 256 * i;
            int kr = lin >> 5, c4 = lin & 31;
            breg[i] = *(const float4*)(W + (size_t)(ch * 32 + kr) * ldw + ncol0 + c4 * 4);
        }
    };
    auto storeB = [&](int buf, const float4* breg) {
        #pragma unroll
        for (int i = 0; i < 4; i++) {
            int lin = tid + 256 * i;
            int kr = lin >> 5, c4 = lin & 31;
            *(uint2*)(smemblk + SB_OFF + buf * 8704 + (kr * 136 + c4 * 4) * 2) =
                pack4h(breg[i]);
        }
    };

    {
        uint4 a0[2];
        float4 b0[4];
        loadA(0, a0);
        loadB(0, b0);
        storeA(0, a0);
        storeB(0, b0);
    }

    for (int ch = 0; ch < CH; ch++) {
        int buf = ch & 1;
        bool more = (ch + 1 < CH);
        uint4 areg[2];
        float4 breg[4];
        if (more) { loadA(ch + 1, areg); loadB(ch + 1, breg); }
        __syncthreads();
        uint32_t bufA = aA + buf * 10240;
        uint32_t bufB = aB + buf * 8704;
        #pragma unroll
        for (int kb = 0; kb < 32; kb += 16) {
            uint32_t a[2][4], bb[4][4];
            #pragma unroll
            for (int mi = 0; mi < 2; mi++)
                ldmx4(a[mi], bufA + offA0 + (uint32_t)((mi * 16 * 40 + kb) * 2));
            #pragma unroll
            for (int g = 0; g < 4; g++)
                ldmx4t(bb[g], bufB + offB0 + (uint32_t)((kb * 136 + g * 16) * 2));
            #pragma unroll
            for (int mi = 0; mi < 2; mi++)
                #pragma unroll
                for (int g = 0; g < 4; g++) {
                    mma16816h(acc[mi][2 * g],     a[mi], &bb[g][0]);
                    mma16816h(acc[mi][2 * g + 1], a[mi], &bb[g][2]);
                }
        }
        if (more) { storeA(buf ^ 1, areg); storeB(buf ^ 1, breg); }
    }
    __syncthreads();

    // epilogue phase 1: stage warp's 32x64 fp16 tile into its smem patch
    char* patch = smemblk + wid * PATCH_STRIDE;
    #pragma unroll
    for (int mi = 0; mi < 2; mi++)
        #pragma unroll
        for (int h = 0; h < 2; h++) {
            int lr = mi * 16 + h * 8 + (lane >> 2);
            int gr = row0 + wm * 32 + lr;
            float dd = (H16 && gr < NN) ? g_dis[gr] : 1.f;
            #pragma unroll
            for (int ni = 0; ni < 8; ni++) {
                int lc = ni * 8 + (lane & 3) * 2;
                int cl = wn * 64 + lc;
                float v0 = acc[mi][ni][2 * h];
                float v1 = acc[mi][ni][2 * h + 1];
                if (HASB) { v0 += bias[cl]; v1 += bias[cl + 1]; }
                if (TANH) { v0 = tanhf(v0); v1 = tanhf(v1); }
                __half2 p = H16 ? __floats2half2_rn(dd * v0, dd * v1)
                                : __floats2half2_rn(v0, v1);
                *(__half2*)(patch + (lr * 72 + lc) * 2) = p;
            }
        }
    __syncwarp();

    // epilogue phase 2: coalesced 128B row stores
    __half* dstbase = H16 ? (__half*)g_h16 : C;
    int ldc = H16 ? 128 : LDC;
    #pragma unroll
    for (int rg = 0; rg < 8; rg++) {
        int lr = rg * 4 + (lane >> 3);
        int seg = lane & 7;
        int gr = row0 + wm * 32 + lr;
        uint4 v = *(uint4*)(patch + (lr * 72 + seg * 8) * 2);
        if (gr < NN)
            *(uint4*)(dstbase + (size_t)gr * ldc + wn * 64 + seg * 8) = v;
    }
}

__global__ void __launch_bounds__(256, 2) gemm_o_mma(const float* __restrict__ Wo) {
    gemm_mma<512, 512, 128, false, false, true>(
        (const __half*)g_act16, Wo, 128, nullptr, nullptr, blockIdx.x * 128, 0);
}

// ---------------- fused dtype detect + degree init ----------------
__global__ void detect_init_kernel(const unsigned int* __restrict__ w) {
    int i = blockIdx.x * blockDim.x + threadIdx.x;
    if (i < NN) g_deg[i] = 1;  // self loop pre-counted
    if (blockIdx.x == 0) {
        // If int64 (LE), high word of every value (<100000) is 0; sample 2048.
        int bad = 0;
        for (int k = threadIdx.x; k < 2048; k += blockDim.x)
            if (w[2 * k + 1] != 0u) bad = 1;
        if (__syncthreads_or(bad)) {
            if (threadIdx.x == 0) g_is64 = 0;
        } else {
            if (threadIdx.x == 0) g_is64 = 1;
        }
    }
}

// ---------------- degree count (4 edges/thread, vectorized decode) -----------
__global__ void count_kernel(const void* __restrict__ ei) {
    int e4 = blockIdx.x * blockDim.x + threadIdx.x;  // quad index
    if (e4 >= EE / 4) return;
    int d0, d1, d2, d3;
    if (g_is64) {
        const longlong2* pd = (const longlong2*)((const long long*)ei + EE);
        longlong2 v0 = pd[2 * e4];
        longlong2 v1 = pd[2 * e4 + 1];
        d0 = (int)v0.x; d1 = (int)v0.y; d2 = (int)v1.x; d3 = (int)v1.y;
    } else {
        const int4* pd = (const int4*)((const int*)ei + EE);
        int4 v = pd[e4];
        d0 = v.x; d1 = v.y; d2 = v.z; d3 = v.w;
    }
    atomicAdd(&g_deg[d0], 1);
    atomicAdd(&g_deg[d1], 1);
    atomicAdd(&g_deg[d2], 1);
    atomicAdd(&g_deg[d3], 1);
}

__global__ void scan1_kernel() {
    __shared__ int sh[1024];
    int i = blockIdx.x * 1024 + threadIdx.x;
    int v = 0;
    if (i < NN) {
        int d = g_deg[i];
        g_dis[i] = rsqrtf((float)d);
        v = d - 1;
    }
    sh[threadIdx.x] = v;
    __syncthreads();
    for (int ofs = 1; ofs < 1024; ofs <<= 1) {
        int t = 0;
        if ((int)threadIdx.x >= ofs) t = sh[threadIdx.x - ofs];
        __syncthreads();
        sh[threadIdx.x] += t;
        __syncthreads();
    }
    int incl = sh[threadIdx.x];
    if (i < NN) g_off[i] = incl - v;  // exclusive within block
    if (threadIdx.x == 1023) g_bsum[blockIdx.x] = incl;
}

// scan3 with scan2 folded in: every block redundantly scans the 98 block sums.
__global__ void scan3_kernel() {
    __shared__ int sh[128];
    int t = threadIdx.x;
    if (t < 128) {
        int v = (t < NB) ? g_bsum[t] : 0;
        sh[t] = v;
        __syncthreads();
        for (int ofs = 1; ofs < 128; ofs <<= 1) {
            int u = (t >= ofs) ? sh[t - ofs] : 0;
            __syncthreads();
            sh[t] += u;
            __syncthreads();
        }
        if (t < 128) sh[t] -= v;  // exclusive
    } else {
        for (int ofs = 1; ofs < 128; ofs <<= 1) { __syncthreads(); __syncthreads(); }
    }
    __syncthreads();
    int base = sh[blockIdx.x];
    int i = blockIdx.x * 1024 + t;
    if (i < NN) {
        int o = g_off[i] + base;
        g_off[i] = o;
        g_cur[i] = o;
    }
    if (i == 0) g_off[NN] = EE;
}

// ---------------- fused scatter (CSR fill, 2 edges/thread) + cast (uint4/thread)
__global__ void __launch_bounds__(256) scatter_cast_kernel(
        const void* __restrict__ ei,
        const float* __restrict__ lat, const float* __restrict__ cond) {
    int b = blockIdx.x;
    if (b < SCAT_BLOCKS) {
        int e2 = b * 256 + threadIdx.x;  // pair index
        if (e2 >= EE / 2) return;
        int s0, s1, d0, d1;
        if (g_is64) {
            const longlong2* ps = (const longlong2*)ei;
            const longlong2* pd = (const longlong2*)((const long long*)ei + EE);
            longlong2 sv = ps[e2];
            longlong2 dv = pd[e2];
            s0 = (int)sv.x; s1 = (int)sv.y;
            d0 = (int)dv.x; d1 = (int)dv.y;
        } else {
            const int2* ps = (const int2*)ei;
            const int2* pd = (const int2*)((const int*)ei + EE);
            int2 sv = ps[e2];
            int2 dv = pd[e2];
            s0 = sv.x; s1 = sv.y;
            d0 = dv.x; d1 = dv.y;
        }
        g_srcs[atomicAdd(&g_cur[d0], 1)] = s0;
        g_srcs[atomicAdd(&g_cur[d1], 1)] = s1;
    } else {
        int t = (b - SCAT_BLOCKS) * 256 + threadIdx.x;  // over NN*32 uint4 slots
        if (t >= NN * 32) return;
        int node = t >> 5;
        int c8 = t & 31;   // which 8-half group of the 256-wide row
        float dd = g_dis[node];
        const float4* src = (c8 < 16)
            ? ((const float4*)lat  + (size_t)node * 32 + 2 * c8)
            : ((const float4*)cond + (size_t)node * 32 + 2 * (c8 - 16));
        float4 v0 = src[0];
        float4 v1 = src[1];
        uint4 o;
        __half2* oh = (__half2*)&o;
        oh[0] = __floats2half2_rn(dd * v0.x, dd * v0.y);
        oh[1] = __floats2half2_rn(dd * v0.z, dd * v0.w);
        oh[2] = __floats2half2_rn(dd * v1.x, dd * v1.y);
        oh[3] = __floats2half2_rn(dd * v1.z, dd * v1.w);
        g_x16[(size_t)node * 32 + c8] = o;
    }
}

// ---------------- unpack-accumulate helpers ----------------
__device__ __forceinline__ void acc8(float* a, uint4 v) {
    const __half2* h = (const __half2*)&v;
    #pragma unroll
    for (int k = 0; k < 4; k++) {
        float2 f = __half22float2(h[k]);
        a[2 * k] += f.x;
        a[2 * k + 1] += f.y;
    }
}
__device__ __forceinline__ void acc4(float* a, uint2 v) {
    const __half2* h = (const __half2*)&v;
    float2 f0 = __half22float2(h[0]);
    float2 f1 = __half22float2(h[1]);
    a[0] += f0.x; a[1] += f0.y; a[2] += f1.x; a[3] += f1.y;
}

// ---------------- aggregation 1: fp16 gather, 512B/node, warp-per-node -----
__global__ void __launch_bounds__(256) aggx_kernel() {
    int gw = (int)((blockIdx.x * blockDim.x + threadIdx.x) >> 5);
    int lane = threadIdx.x & 31;
    if (gw >= NN) return;
    float dd = g_dis[gw];
    float a[8];
    #pragma unroll
    for (int k = 0; k < 8; k++) a[k] = 0.f;
    acc8(a, g_x16[(size_t)gw * 32 + lane]);  // self term (pre-scaled by dis)
    int beg = g_off[gw], end = g_off[gw + 1];
    #pragma unroll 8
    for (int j = beg; j < end; ++j) {
        int s = g_srcs[j];
        acc8(a, g_x16[(size_t)s * 32 + lane]);
    }
    uint4 o;
    __half2* oh = (__half2*)&o;
    #pragma unroll
    for (int k = 0; k < 4; k++)
        oh[k] = __floats2half2_rn(dd * a[2 * k], dd * a[2 * k + 1]);
    g_xagg16[(size_t)gw * 32 + lane] = o;
}

// ---------------- aggregation 2: fp16 gather, 256B/node, warp-per-node -----
__global__ void __launch_bounds__(256) agg2_kernel(const float* __restrict__ bo,
                                                   float* __restrict__ out) {
    int gw = (int)((blockIdx.x * blockDim.x + threadIdx.x) >> 5);
    int lane = threadIdx.x & 31;
    if (gw >= NN) return;
    float dd = g_dis[gw];
    float a[4];
    #pragma unroll
    for (int k = 0; k < 4; k++) a[k] = 0.f;
    acc4(a, g_h16[(size_t)gw * 32 + lane]);  // self term
    int beg = g_off[gw], end = g_off[gw + 1];
    #pragma unroll 8
    for (int j = beg; j < end; ++j) {
        int s = g_srcs[j];
        acc4(a, g_h16[(size_t)s * 32 + lane]);
    }
    float4 b = ((const float4*)bo)[lane];
    ((float4*)out)[(size_t)gw * 32 + lane] =
        make_float4(dd * a[0] + b.x, dd * a[1] + b.y, dd * a[2] + b.z, dd * a[3] + b.w);
}

// ---------------- launch ----------------
extern "C" void kernel_launch(void* const* d_in, const int* in_sizes, int n_in,
                              void* d_out, int out_size) {
    const float* latent    = (const float*)d_in[0];
    const float* condition = (const float*)d_in[1];
    const void*  ei        = d_in[2];
    const float* Wz = (const float*)d_in[3];
    const float* bz = (const float*)d_in[4];
    const float* Wc = (const float*)d_in[5];
    const float* bc = (const float*)d_in[6];
    const float* Wo = (const float*)d_in[7];
    const float* bo = (const float*)d_in[8];
    float* out = (float*)d_out;

    detect_init_kernel<<<(NN + 255) / 256, 256>>>((const unsigned int*)ei);
    count_kernel<<<(EE / 4 + 255) / 256, 256>>>(ei);
    scan1_kernel<<<NB, 1024>>>();
    scan3_kernel<<<NB, 1024>>>();
    scatter_cast_kernel<<<SCAT_BLOCKS + CAST_BLOCKS, 256>>>(ei, latent, condition);
    aggx_kernel<<<(NN * 32 + 255) / 256, 256>>>();

    gemm_zc_mma<<<dim3(ZC_CTAX, 2, 2), 256>>>(Wz, bz, Wc, bc);
    int ntiles = (NN + 127) / 128;  // 782
    gemm_o_mma<<<ntiles, 256>>>(Wo);

    agg2_kernel<<<(NN * 32 + 255) / 256, 256>>>(bo, out);
}